// round 4
// baseline (speedup 1.0000x reference)
#include <cuda_runtime.h>
#include <cstdint>

// Problem constants (match reference_code)
#define NROWS 100001
#define DIM   64
#define NNZ_E 3200000
#define ND    (NROWS * DIM)          // floats per segment
#define ND4   (ND / 4)               // float4 per segment
#define SCAN_B 1024
#define NBLK  ((NROWS + SCAN_B - 1) / SCAN_B)   // 98

// ---------------------------------------------------------------------------
// Static device scratch (no allocations allowed in kernel_launch).
// ---------------------------------------------------------------------------
__device__ int  g_counts[NROWS];        // histogram, then scatter cursors
__device__ int  g_rowptr[NROWS + 1];    // CSR row pointers (exclusive scan)
__device__ int  g_blk_agg[NBLK];        // lookback: block aggregate
__device__ int  g_blk_pre[NBLK];        // lookback: inclusive prefix
__device__ int  g_blk_flag[NBLK];       // lookback: 0=none, 1=agg, 2=prefix
__device__ int2 g_meta[NNZ_E];          // CSR-ordered (col, val-bits), 25.6MB

// ---------------------------------------------------------------------------
// K1: zero histogram + lookback flags.
// ---------------------------------------------------------------------------
__global__ void zero_kernel()
{
    int i = blockIdx.x * blockDim.x + threadIdx.x;
    if (i < NROWS) g_counts[i] = 0;
    if (i < NBLK) g_blk_flag[i] = 0;
    if (i == 0) g_rowptr[NROWS] = NNZ_E;
}

// ---------------------------------------------------------------------------
// K2: histogram of row indices, 4 edges/thread via int4 (NNZ_E % 4 == 0).
// ---------------------------------------------------------------------------
__global__ void hist_kernel(const int4* __restrict__ row4)
{
    int i = blockIdx.x * blockDim.x + threadIdx.x;
    if (i < NNZ_E / 4) {
        int4 r = __ldg(row4 + i);
        atomicAdd(&g_counts[r.x], 1);
        atomicAdd(&g_counts[r.y], 1);
        atomicAdd(&g_counts[r.z], 1);
        atomicAdd(&g_counts[r.w], 1);
    }
}

// ---------------------------------------------------------------------------
// K3: single-pass decoupled-lookback exclusive scan.
//     counts -> rowptr (exclusive) and counts (scatter cursors).
//     98 blocks, all resident simultaneously -> spin-wait is safe.
// ---------------------------------------------------------------------------
__global__ void scan_lookback_kernel()
{
    __shared__ int s[SCAN_B];
    __shared__ int base_sh;
    int gid = blockIdx.x * SCAN_B + threadIdx.x;
    int v = (gid < NROWS) ? g_counts[gid] : 0;
    s[threadIdx.x] = v;
    __syncthreads();
    #pragma unroll
    for (int off = 1; off < SCAN_B; off <<= 1) {
        int t = (threadIdx.x >= off) ? s[threadIdx.x - off] : 0;
        __syncthreads();
        s[threadIdx.x] += t;
        __syncthreads();
    }
    int incl = s[threadIdx.x];

    if (threadIdx.x == SCAN_B - 1) {
        int agg = incl;                      // block total
        int b = blockIdx.x;
        if (b == 0) {
            g_blk_pre[0] = agg;
            __threadfence();
            atomicExch(&g_blk_flag[0], 2);
            base_sh = 0;
        } else {
            g_blk_agg[b] = agg;
            __threadfence();
            atomicExch(&g_blk_flag[b], 1);
            int base = 0;
            int p = b - 1;
            while (true) {
                int f;
                do { f = atomicAdd(&g_blk_flag[p], 0); } while (f == 0);
                if (f == 2) { base += atomicAdd(&g_blk_pre[p], 0); break; }
                base += atomicAdd(&g_blk_agg[p], 0);
                p--;
            }
            g_blk_pre[b] = base + agg;
            __threadfence();
            atomicExch(&g_blk_flag[b], 2);
            base_sh = base;
        }
    }
    __syncthreads();

    if (gid < NROWS) {
        int ex = base_sh + incl - v;        // exclusive prefix
        g_rowptr[gid] = ex;
        g_counts[gid] = ex;                 // scatter cursor
    }
}

// ---------------------------------------------------------------------------
// K4: scatter edges into CSR order (order within a row irrelevant).
// ---------------------------------------------------------------------------
__global__ void scatter_kernel(const int* __restrict__ row,
                               const int* __restrict__ col,
                               const float* __restrict__ vals)
{
    int e = blockIdx.x * blockDim.x + threadIdx.x;
    if (e < NNZ_E) {
        int r = __ldg(row + e);
        int pos = atomicAdd(&g_counts[r], 1);
        g_meta[pos] = make_int2(__ldg(col + e), __float_as_int(__ldg(vals + e)));
    }
}

// ---------------------------------------------------------------------------
// K5: CSR SpMM, one warp per row, half-warps take alternating edges,
//     4-deep pipelined inner loop (8 loads in flight per thread).
//   y[r,:] = sum_e vals[e] * x[col[e],:]
//   COPY_E0: also e0[r,:] = x[r,:]           (layer 1, x == emb)
//   FUSE:    also summed[r,:] = e0 + e1 + y  (layer 2)
// ---------------------------------------------------------------------------
template <bool COPY_E0, bool FUSE>
__global__ void spmm_csr_kernel(const float4* __restrict__ x,
                                float4* __restrict__ y,
                                float4* __restrict__ e0_out,
                                const float4* __restrict__ e0,
                                const float4* __restrict__ e1,
                                float4* __restrict__ summed)
{
    int warp = (blockIdx.x * blockDim.x + threadIdx.x) >> 5;
    int lane = threadIdx.x & 31;
    int j    = lane & 15;        // float4 slot within the 64-wide row
    int half = lane >> 4;        // 0 or 1: which edge of the pair
    if (warp >= NROWS) return;
    int r = warp;

    int beg = g_rowptr[r];
    int end = g_rowptr[r + 1];

    float4 acc = make_float4(0.f, 0.f, 0.f, 0.f);
    int e = beg + half;          // this thread's edge stream: e, e+2, e+4, ...

    // 4-deep: edges e, e+2, e+4, e+6 concurrently
    for (; e + 6 < end; e += 8) {
        int2 m0 = __ldg(&g_meta[e]);
        int2 m1 = __ldg(&g_meta[e + 2]);
        int2 m2 = __ldg(&g_meta[e + 4]);
        int2 m3 = __ldg(&g_meta[e + 6]);
        float4 x0 = __ldg(x + (size_t)m0.x * 16 + j);
        float4 x1 = __ldg(x + (size_t)m1.x * 16 + j);
        float4 x2 = __ldg(x + (size_t)m2.x * 16 + j);
        float4 x3 = __ldg(x + (size_t)m3.x * 16 + j);
        float v0 = __int_as_float(m0.y);
        float v1 = __int_as_float(m1.y);
        float v2 = __int_as_float(m2.y);
        float v3 = __int_as_float(m3.y);
        acc.x = fmaf(v0, x0.x, acc.x); acc.y = fmaf(v0, x0.y, acc.y);
        acc.z = fmaf(v0, x0.z, acc.z); acc.w = fmaf(v0, x0.w, acc.w);
        acc.x = fmaf(v1, x1.x, acc.x); acc.y = fmaf(v1, x1.y, acc.y);
        acc.z = fmaf(v1, x1.z, acc.z); acc.w = fmaf(v1, x1.w, acc.w);
        acc.x = fmaf(v2, x2.x, acc.x); acc.y = fmaf(v2, x2.y, acc.y);
        acc.z = fmaf(v2, x2.z, acc.z); acc.w = fmaf(v2, x2.w, acc.w);
        acc.x = fmaf(v3, x3.x, acc.x); acc.y = fmaf(v3, x3.y, acc.y);
        acc.z = fmaf(v3, x3.z, acc.z); acc.w = fmaf(v3, x3.w, acc.w);
    }
    // 2-deep remainder
    for (; e + 2 < end; e += 4) {
        int2 m0 = __ldg(&g_meta[e]);
        int2 m1 = __ldg(&g_meta[e + 2]);
        float4 x0 = __ldg(x + (size_t)m0.x * 16 + j);
        float4 x1 = __ldg(x + (size_t)m1.x * 16 + j);
        float v0 = __int_as_float(m0.y);
        float v1 = __int_as_float(m1.y);
        acc.x = fmaf(v0, x0.x, acc.x); acc.y = fmaf(v0, x0.y, acc.y);
        acc.z = fmaf(v0, x0.z, acc.z); acc.w = fmaf(v0, x0.w, acc.w);
        acc.x = fmaf(v1, x1.x, acc.x); acc.y = fmaf(v1, x1.y, acc.y);
        acc.z = fmaf(v1, x1.z, acc.z); acc.w = fmaf(v1, x1.w, acc.w);
    }
    if (e < end) {
        int2 m0 = __ldg(&g_meta[e]);
        float4 x0 = __ldg(x + (size_t)m0.x * 16 + j);
        float v0 = __int_as_float(m0.y);
        acc.x = fmaf(v0, x0.x, acc.x); acc.y = fmaf(v0, x0.y, acc.y);
        acc.z = fmaf(v0, x0.z, acc.z); acc.w = fmaf(v0, x0.w, acc.w);
    }

    // combine the two half-warp partials
    acc.x += __shfl_xor_sync(0xffffffffu, acc.x, 16);
    acc.y += __shfl_xor_sync(0xffffffffu, acc.y, 16);
    acc.z += __shfl_xor_sync(0xffffffffu, acc.z, 16);
    acc.w += __shfl_xor_sync(0xffffffffu, acc.w, 16);

    if (half == 0) {
        size_t o = (size_t)r * 16 + j;
        y[o] = acc;
        if (COPY_E0) {
            e0_out[o] = __ldg(x + o);       // e0 = emb (row-contiguous copy)
        }
        if (FUSE) {
            float4 a = e0[o];
            float4 b = e1[o];
            float4 s;
            s.x = a.x + b.x + acc.x;
            s.y = a.y + b.y + acc.y;
            s.z = a.z + b.z + acc.z;
            s.w = a.w + b.w + acc.w;
            summed[o] = s;
        }
    }
}

// ---------------------------------------------------------------------------
// Launch sequence (default stream, graph-capturable, no allocations):
//   zero -> hist -> lookback scan -> scatter -> spmm L1 (+e0) -> spmm L2 (+sum)
// ---------------------------------------------------------------------------
extern "C" void kernel_launch(void* const* d_in, const int* in_sizes, int n_in,
                              void* d_out, int out_size)
{
    const int*   row  = (const int*)d_in[0];
    const int*   col  = (const int*)d_in[1];
    const float* vals = (const float*)d_in[2];
    const float* emb  = (const float*)d_in[3];

    float* out = (float*)d_out;
    float4* summed = (float4*)out;
    float4* e0 = (float4*)(out + (size_t)ND);
    float4* e1 = (float4*)(out + (size_t)2 * ND);
    float4* e2 = (float4*)(out + (size_t)3 * ND);

    const int TPB = 256;

    // K1: zero counts + flags
    zero_kernel<<<(NROWS + TPB - 1) / TPB, TPB>>>();

    // K2: histogram (4 edges per thread)
    hist_kernel<<<(NNZ_E / 4 + TPB - 1) / TPB, TPB>>>((const int4*)row);

    // K3: single-pass decoupled-lookback exclusive scan
    scan_lookback_kernel<<<NBLK, SCAN_B>>>();

    // K4: scatter to CSR
    scatter_kernel<<<(NNZ_E + TPB - 1) / TPB, TPB>>>(row, col, vals);

    // K5/K6: warp per row
    const int WARPS_PER_BLOCK = TPB / 32;
    int spmm_blocks = (NROWS + WARPS_PER_BLOCK - 1) / WARPS_PER_BLOCK;

    // layer 1: e1 = A @ emb, fused e0 = emb
    spmm_csr_kernel<true, false><<<spmm_blocks, TPB>>>(
        (const float4*)emb, e1, e0, nullptr, nullptr, nullptr);

    // layer 2: e2 = A @ e1, fused summed = e0 + e1 + e2
    spmm_csr_kernel<false, true><<<spmm_blocks, TPB>>>(
        (const float4*)e1, e2, nullptr, (const float4*)e0,
        (const float4*)e1, summed);
}

// round 5
// speedup vs baseline: 1.0253x; 1.0253x over previous
#include <cuda_runtime.h>
#include <cstdint>

// Problem constants (match reference_code)
#define NROWS 100001
#define DIM   64
#define NNZ_E 3200000
#define ND    (NROWS * DIM)          // floats per segment
#define ND4   (ND / 4)               // float4 per segment
#define SCAN_B 1024
#define NBLK  ((NROWS + SCAN_B - 1) / SCAN_B)   // 98

// ---------------------------------------------------------------------------
// Static device scratch (no allocations allowed in kernel_launch).
// ---------------------------------------------------------------------------
__device__ int  g_counts[NROWS];        // histogram, then scatter cursors
__device__ int  g_rowptr[NROWS + 1];    // CSR row pointers (exclusive scan)
__device__ int  g_partials[NBLK];       // scan block partials
__device__ int2 g_meta[NNZ_E];          // CSR-ordered (col, val-bits), 25.6MB

// ---------------------------------------------------------------------------
// K1: zero histogram (tiny).
// ---------------------------------------------------------------------------
__global__ void zero_kernel()
{
    int i = blockIdx.x * blockDim.x + threadIdx.x;
    if (i < NROWS) g_counts[i] = 0;
    if (i == 0) g_rowptr[NROWS] = NNZ_E;
}

// ---------------------------------------------------------------------------
// K2: histogram of row indices, 4 edges/thread via int4 (NNZ_E % 4 == 0).
//     (return value unused -> compiles to REDG, no return latency)
// ---------------------------------------------------------------------------
__global__ void hist_kernel(const int4* __restrict__ row4)
{
    int i = blockIdx.x * blockDim.x + threadIdx.x;
    if (i < NNZ_E / 4) {
        int4 r = __ldg(row4 + i);
        atomicAdd(&g_counts[r.x], 1);
        atomicAdd(&g_counts[r.y], 1);
        atomicAdd(&g_counts[r.z], 1);
        atomicAdd(&g_counts[r.w], 1);
    }
}

// ---------------------------------------------------------------------------
// K3a: per-block exclusive scan of counts -> rowptr (block-local) + partials.
// ---------------------------------------------------------------------------
__global__ void scan1_kernel()
{
    __shared__ int s[SCAN_B];
    int gid = blockIdx.x * SCAN_B + threadIdx.x;
    int v = (gid < NROWS) ? g_counts[gid] : 0;
    s[threadIdx.x] = v;
    __syncthreads();
    #pragma unroll
    for (int off = 1; off < SCAN_B; off <<= 1) {
        int t = (threadIdx.x >= off) ? s[threadIdx.x - off] : 0;
        __syncthreads();
        s[threadIdx.x] += t;
        __syncthreads();
    }
    if (gid < NROWS) g_rowptr[gid] = s[threadIdx.x] - v;   // exclusive
    if (threadIdx.x == SCAN_B - 1) g_partials[blockIdx.x] = s[threadIdx.x];
}

// K3b: exclusive scan of the 98 partials (one 128-thread block, parallel).
__global__ void scan2_kernel()
{
    __shared__ int s[128];
    int t = threadIdx.x;
    int v = (t < NBLK) ? g_partials[t] : 0;
    s[t] = v;
    __syncthreads();
    #pragma unroll
    for (int off = 1; off < 128; off <<= 1) {
        int u = (t >= off) ? s[t - off] : 0;
        __syncthreads();
        s[t] += u;
        __syncthreads();
    }
    if (t < NBLK) g_partials[t] = s[t] - v;   // exclusive
}

// K3c: add block bases; duplicate rowptr into counts as scatter cursors.
__global__ void scan3_kernel()
{
    int gid = blockIdx.x * SCAN_B + threadIdx.x;
    if (gid < NROWS) {
        int p = g_rowptr[gid] + g_partials[blockIdx.x];
        g_rowptr[gid] = p;
        g_counts[gid] = p;
    }
}

// ---------------------------------------------------------------------------
// K4: scatter edges into CSR order, 4 EDGES PER THREAD.
//     4 independent ATOMG cursor bumps in flight (MLP=4) hides the 318-cyc
//     atomic return latency that bound the 1-edge/thread version.
// ---------------------------------------------------------------------------
__global__ void scatter_kernel(const int4* __restrict__ row4,
                               const int4* __restrict__ col4,
                               const float4* __restrict__ vals4)
{
    int i = blockIdx.x * blockDim.x + threadIdx.x;
    if (i < NNZ_E / 4) {
        int4   r = __ldg(row4 + i);
        int4   c = __ldg(col4 + i);
        float4 v = __ldg(vals4 + i);
        int p0 = atomicAdd(&g_counts[r.x], 1);
        int p1 = atomicAdd(&g_counts[r.y], 1);
        int p2 = atomicAdd(&g_counts[r.z], 1);
        int p3 = atomicAdd(&g_counts[r.w], 1);
        g_meta[p0] = make_int2(c.x, __float_as_int(v.x));
        g_meta[p1] = make_int2(c.y, __float_as_int(v.y));
        g_meta[p2] = make_int2(c.z, __float_as_int(v.z));
        g_meta[p3] = make_int2(c.w, __float_as_int(v.w));
    }
}

// ---------------------------------------------------------------------------
// K5: CSR SpMM, one warp per row, half-warps take alternating edges,
//     2-deep pipelined inner loop, register accumulation, shfl combine.
//   y[r,:] = sum_e vals[e] * x[col[e],:]
//   COPY_E0: also e0[r,:] = x[r,:]           (layer 1, x == emb)
//   FUSE:    also summed[r,:] = e0 + e1 + y  (layer 2)
// ---------------------------------------------------------------------------
template <bool COPY_E0, bool FUSE>
__global__ void spmm_csr_kernel(const float4* __restrict__ x,
                                float4* __restrict__ y,
                                float4* __restrict__ e0_out,
                                const float4* __restrict__ e0,
                                const float4* __restrict__ e1,
                                float4* __restrict__ summed)
{
    int warp = (blockIdx.x * blockDim.x + threadIdx.x) >> 5;
    int lane = threadIdx.x & 31;
    int j    = lane & 15;        // float4 slot within the 64-wide row
    int half = lane >> 4;        // 0 or 1: which edge of the pair
    if (warp >= NROWS) return;
    int r = warp;

    int beg = g_rowptr[r];
    int end = g_rowptr[r + 1];

    float4 acc = make_float4(0.f, 0.f, 0.f, 0.f);
    int e = beg + half;          // this thread's edge stream: e, e+2, e+4, ...
    // 2-way unroll: edges e and e+2 in flight (4 gathers per warp iteration)
    for (; e + 2 < end; e += 4) {
        int2 m0 = __ldg(&g_meta[e]);
        int2 m1 = __ldg(&g_meta[e + 2]);
        float4 x0 = __ldg(x + (size_t)m0.x * 16 + j);
        float4 x1 = __ldg(x + (size_t)m1.x * 16 + j);
        float v0 = __int_as_float(m0.y);
        float v1 = __int_as_float(m1.y);
        acc.x = fmaf(v0, x0.x, acc.x); acc.y = fmaf(v0, x0.y, acc.y);
        acc.z = fmaf(v0, x0.z, acc.z); acc.w = fmaf(v0, x0.w, acc.w);
        acc.x = fmaf(v1, x1.x, acc.x); acc.y = fmaf(v1, x1.y, acc.y);
        acc.z = fmaf(v1, x1.z, acc.z); acc.w = fmaf(v1, x1.w, acc.w);
    }
    if (e < end) {
        int2 m0 = __ldg(&g_meta[e]);
        float4 x0 = __ldg(x + (size_t)m0.x * 16 + j);
        float v0 = __int_as_float(m0.y);
        acc.x = fmaf(v0, x0.x, acc.x); acc.y = fmaf(v0, x0.y, acc.y);
        acc.z = fmaf(v0, x0.z, acc.z); acc.w = fmaf(v0, x0.w, acc.w);
    }

    // combine the two half-warp partials
    acc.x += __shfl_xor_sync(0xffffffffu, acc.x, 16);
    acc.y += __shfl_xor_sync(0xffffffffu, acc.y, 16);
    acc.z += __shfl_xor_sync(0xffffffffu, acc.z, 16);
    acc.w += __shfl_xor_sync(0xffffffffu, acc.w, 16);

    if (half == 0) {
        size_t o = (size_t)r * 16 + j;
        y[o] = acc;
        if (COPY_E0) {
            e0_out[o] = __ldg(x + o);       // e0 = emb (row-contiguous copy)
        }
        if (FUSE) {
            float4 a = e0[o];
            float4 b = e1[o];
            float4 s;
            s.x = a.x + b.x + acc.x;
            s.y = a.y + b.y + acc.y;
            s.z = a.z + b.z + acc.z;
            s.w = a.w + b.w + acc.w;
            summed[o] = s;
        }
    }
}

// ---------------------------------------------------------------------------
// Launch sequence (default stream, graph-capturable, no allocations):
//   zero -> hist -> scan(3) -> scatter -> spmm L1 (+e0) -> spmm L2 (+sum)
// ---------------------------------------------------------------------------
extern "C" void kernel_launch(void* const* d_in, const int* in_sizes, int n_in,
                              void* d_out, int out_size)
{
    const int*   row  = (const int*)d_in[0];
    const int*   col  = (const int*)d_in[1];
    const float* vals = (const float*)d_in[2];
    const float* emb  = (const float*)d_in[3];

    float* out = (float*)d_out;
    float4* summed = (float4*)out;
    float4* e0 = (float4*)(out + (size_t)ND);
    float4* e1 = (float4*)(out + (size_t)2 * ND);
    float4* e2 = (float4*)(out + (size_t)3 * ND);

    const int TPB = 256;

    // K1: zero counts
    zero_kernel<<<(NROWS + TPB - 1) / TPB, TPB>>>();

    // K2: histogram (4 edges per thread)
    hist_kernel<<<(NNZ_E / 4 + TPB - 1) / TPB, TPB>>>((const int4*)row);

    // K3: exclusive scan -> rowptr + cursors
    scan1_kernel<<<NBLK, SCAN_B>>>();
    scan2_kernel<<<1, 128>>>();
    scan3_kernel<<<NBLK, SCAN_B>>>();

    // K4: scatter to CSR (4 edges per thread, MLP=4 on atomics)
    scatter_kernel<<<(NNZ_E / 4 + TPB - 1) / TPB, TPB>>>(
        (const int4*)row, (const int4*)col, (const float4*)vals);

    // K5/K6: warp per row
    const int WARPS_PER_BLOCK = TPB / 32;
    int spmm_blocks = (NROWS + WARPS_PER_BLOCK - 1) / WARPS_PER_BLOCK;

    // layer 1: e1 = A @ emb, fused e0 = emb
    spmm_csr_kernel<true, false><<<spmm_blocks, TPB>>>(
        (const float4*)emb, e1, e0, nullptr, nullptr, nullptr);

    // layer 2: e2 = A @ e1, fused summed = e0 + e1 + e2
    spmm_csr_kernel<false, true><<<spmm_blocks, TPB>>>(
        (const float4*)e1, e2, nullptr, (const float4*)e0,
        (const float4*)e1, summed);
}

// round 7
// speedup vs baseline: 1.2068x; 1.1770x over previous
#include <cuda_runtime.h>
#include <cuda_fp16.h>
#include <cstdint>

// Problem constants (match reference_code)
#define NROWS 100001
#define DIM   64
#define NNZ_E 3200000
#define ND    (NROWS * DIM)          // floats per segment
#define ND4   (ND / 4)               // float4 per segment
#define SCAN_B 1024
#define NBLK  ((NROWS + SCAN_B - 1) / SCAN_B)   // 98

// ---------------------------------------------------------------------------
// Static device scratch (no allocations allowed in kernel_launch).
// NOTE: these symbols are referenced ONLY inside device code. Passing a
// __device__ array as a kernel argument from host code yields the host-side
// shadow address (garbage on device) — that was the Round-6 bug.
// ---------------------------------------------------------------------------
__device__ int   g_counts[NROWS];       // histogram, then scatter cursors
__device__ int   g_rowptr[NROWS + 1];   // CSR row pointers (exclusive scan)
__device__ int   g_partials[NBLK];      // scan block partials
__device__ int2  g_meta[NNZ_E];         // CSR-ordered (col, val-bits), 25.6MB
__device__ uint2 g_embh[ND / 4];        // emb in fp16 (4 halves per uint2), 12.8MB
__device__ uint2 g_e1h[ND / 4];         // e1  in fp16, 12.8MB

// ---------------------------------------------------------------------------
// K1: prep — e0 = emb (fp32 copy), embh = fp16(emb), zero histogram.
// ---------------------------------------------------------------------------
__global__ void prep_kernel(const float4* __restrict__ emb,
                            float4* __restrict__ e0)
{
    int i = blockIdx.x * blockDim.x + threadIdx.x;
    if (i < ND4) {
        float4 v = __ldg(emb + i);
        e0[i] = v;
        __half2 h0 = __floats2half2_rn(v.x, v.y);
        __half2 h1 = __floats2half2_rn(v.z, v.w);
        uint2 u;
        u.x = *reinterpret_cast<unsigned*>(&h0);
        u.y = *reinterpret_cast<unsigned*>(&h1);
        g_embh[i] = u;
    }
    if (i < NROWS) g_counts[i] = 0;
    if (i == 0) g_rowptr[NROWS] = NNZ_E;
}

// ---------------------------------------------------------------------------
// K2: histogram of row indices, 4 edges/thread via int4 (NNZ_E % 4 == 0).
// ---------------------------------------------------------------------------
__global__ void hist_kernel(const int4* __restrict__ row4)
{
    int i = blockIdx.x * blockDim.x + threadIdx.x;
    if (i < NNZ_E / 4) {
        int4 r = __ldg(row4 + i);
        atomicAdd(&g_counts[r.x], 1);
        atomicAdd(&g_counts[r.y], 1);
        atomicAdd(&g_counts[r.z], 1);
        atomicAdd(&g_counts[r.w], 1);
    }
}

// ---------------------------------------------------------------------------
// K3a/b/c: exclusive scan of counts -> rowptr + scatter cursors.
// ---------------------------------------------------------------------------
__global__ void scan1_kernel()
{
    __shared__ int s[SCAN_B];
    int gid = blockIdx.x * SCAN_B + threadIdx.x;
    int v = (gid < NROWS) ? g_counts[gid] : 0;
    s[threadIdx.x] = v;
    __syncthreads();
    #pragma unroll
    for (int off = 1; off < SCAN_B; off <<= 1) {
        int t = (threadIdx.x >= off) ? s[threadIdx.x - off] : 0;
        __syncthreads();
        s[threadIdx.x] += t;
        __syncthreads();
    }
    if (gid < NROWS) g_rowptr[gid] = s[threadIdx.x] - v;   // exclusive
    if (threadIdx.x == SCAN_B - 1) g_partials[blockIdx.x] = s[threadIdx.x];
}

__global__ void scan2_kernel()
{
    __shared__ int s[128];
    int t = threadIdx.x;
    int v = (t < NBLK) ? g_partials[t] : 0;
    s[t] = v;
    __syncthreads();
    #pragma unroll
    for (int off = 1; off < 128; off <<= 1) {
        int u = (t >= off) ? s[t - off] : 0;
        __syncthreads();
        s[t] += u;
        __syncthreads();
    }
    if (t < NBLK) g_partials[t] = s[t] - v;   // exclusive
}

__global__ void scan3_kernel()
{
    int gid = blockIdx.x * SCAN_B + threadIdx.x;
    if (gid < NROWS) {
        int p = g_rowptr[gid] + g_partials[blockIdx.x];
        g_rowptr[gid] = p;
        g_counts[gid] = p;
    }
}

// ---------------------------------------------------------------------------
// K4: scatter edges into CSR order, 4 edges per thread (MLP=4 on atomics).
// ---------------------------------------------------------------------------
__global__ void scatter_kernel(const int4* __restrict__ row4,
                               const int4* __restrict__ col4,
                               const float4* __restrict__ vals4)
{
    int i = blockIdx.x * blockDim.x + threadIdx.x;
    if (i < NNZ_E / 4) {
        int4   r = __ldg(row4 + i);
        int4   c = __ldg(col4 + i);
        float4 v = __ldg(vals4 + i);
        int p0 = atomicAdd(&g_counts[r.x], 1);
        int p1 = atomicAdd(&g_counts[r.y], 1);
        int p2 = atomicAdd(&g_counts[r.z], 1);
        int p3 = atomicAdd(&g_counts[r.w], 1);
        g_meta[p0] = make_int2(c.x, __float_as_int(v.x));
        g_meta[p1] = make_int2(c.y, __float_as_int(v.y));
        g_meta[p2] = make_int2(c.z, __float_as_int(v.z));
        g_meta[p3] = make_int2(c.w, __float_as_int(v.w));
    }
}

// ---------------------------------------------------------------------------
// K5: CSR SpMM with FP16 GATHERS, fp32 accumulation.
//     SRC selects the gather source INSIDE device code (0=g_embh, 1=g_e1h).
//     One warp per row; half-warps take alternating edges; 2-deep pipeline;
//     shfl combine; single fp32 store.
//   y[r,:] = sum_e vals[e] * half2float(src[col[e],:])
//   WRITE_H: also g_e1h[r,:] = fp16(y[r,:])   (layer 1 -> feeds layer 2)
//   FUSE:    also summed[r,:] = e0 + e1 + y   (layer 2)
// ---------------------------------------------------------------------------
template <int SRC, bool WRITE_H, bool FUSE>
__global__ void spmm_csr_kernel(float4* __restrict__ y,
                                const float4* __restrict__ e0,
                                const float4* __restrict__ e1,
                                float4* __restrict__ summed)
{
    const uint2* __restrict__ xh = (SRC == 0) ? g_embh : g_e1h;

    int warp = (blockIdx.x * blockDim.x + threadIdx.x) >> 5;
    int lane = threadIdx.x & 31;
    int j    = lane & 15;        // 4-half slot within the 64-wide row
    int half = lane >> 4;        // 0 or 1: which edge of the pair
    if (warp >= NROWS) return;
    int r = warp;

    int beg = g_rowptr[r];
    int end = g_rowptr[r + 1];

    float4 acc = make_float4(0.f, 0.f, 0.f, 0.f);
    int e = beg + half;          // this thread's edge stream: e, e+2, e+4, ...
    for (; e + 2 < end; e += 4) {
        int2 m0 = __ldg(&g_meta[e]);
        int2 m1 = __ldg(&g_meta[e + 2]);
        uint2 u0 = __ldg(xh + (size_t)m0.x * 16 + j);
        uint2 u1 = __ldg(xh + (size_t)m1.x * 16 + j);
        float v0 = __int_as_float(m0.y);
        float v1 = __int_as_float(m1.y);
        float2 a0 = __half22float2(*reinterpret_cast<__half2*>(&u0.x));
        float2 b0 = __half22float2(*reinterpret_cast<__half2*>(&u0.y));
        float2 a1 = __half22float2(*reinterpret_cast<__half2*>(&u1.x));
        float2 b1 = __half22float2(*reinterpret_cast<__half2*>(&u1.y));
        acc.x = fmaf(v0, a0.x, acc.x); acc.y = fmaf(v0, a0.y, acc.y);
        acc.z = fmaf(v0, b0.x, acc.z); acc.w = fmaf(v0, b0.y, acc.w);
        acc.x = fmaf(v1, a1.x, acc.x); acc.y = fmaf(v1, a1.y, acc.y);
        acc.z = fmaf(v1, b1.x, acc.z); acc.w = fmaf(v1, b1.y, acc.w);
    }
    if (e < end) {
        int2 m0 = __ldg(&g_meta[e]);
        uint2 u0 = __ldg(xh + (size_t)m0.x * 16 + j);
        float v0 = __int_as_float(m0.y);
        float2 a0 = __half22float2(*reinterpret_cast<__half2*>(&u0.x));
        float2 b0 = __half22float2(*reinterpret_cast<__half2*>(&u0.y));
        acc.x = fmaf(v0, a0.x, acc.x); acc.y = fmaf(v0, a0.y, acc.y);
        acc.z = fmaf(v0, b0.x, acc.z); acc.w = fmaf(v0, b0.y, acc.w);
    }

    // combine the two half-warp partials
    acc.x += __shfl_xor_sync(0xffffffffu, acc.x, 16);
    acc.y += __shfl_xor_sync(0xffffffffu, acc.y, 16);
    acc.z += __shfl_xor_sync(0xffffffffu, acc.z, 16);
    acc.w += __shfl_xor_sync(0xffffffffu, acc.w, 16);

    if (half == 0) {
        size_t o = (size_t)r * 16 + j;
        y[o] = acc;
        if (WRITE_H) {
            __half2 h0 = __floats2half2_rn(acc.x, acc.y);
            __half2 h1 = __floats2half2_rn(acc.z, acc.w);
            uint2 u;
            u.x = *reinterpret_cast<unsigned*>(&h0);
            u.y = *reinterpret_cast<unsigned*>(&h1);
            g_e1h[o] = u;
        }
        if (FUSE) {
            float4 a = __ldg(e0 + o);
            float4 b = __ldg(e1 + o);
            float4 s;
            s.x = a.x + b.x + acc.x;
            s.y = a.y + b.y + acc.y;
            s.z = a.z + b.z + acc.z;
            s.w = a.w + b.w + acc.w;
            summed[o] = s;
        }
    }
}

// ---------------------------------------------------------------------------
// Launch sequence (default stream, graph-capturable, no allocations):
//   prep -> hist -> scan(3) -> scatter -> spmm L1 (fp16 out) -> spmm L2 (+sum)
// ---------------------------------------------------------------------------
extern "C" void kernel_launch(void* const* d_in, const int* in_sizes, int n_in,
                              void* d_out, int out_size)
{
    const int*   row  = (const int*)d_in[0];
    const int*   col  = (const int*)d_in[1];
    const float* vals = (const float*)d_in[2];
    const float* emb  = (const float*)d_in[3];

    float* out = (float*)d_out;
    float4* summed = (float4*)out;
    float4* e0 = (float4*)(out + (size_t)ND);
    float4* e1 = (float4*)(out + (size_t)2 * ND);
    float4* e2 = (float4*)(out + (size_t)3 * ND);

    const int TPB = 256;

    // K1: e0 copy + fp16 conversion + zero counts
    prep_kernel<<<(ND4 + TPB - 1) / TPB, TPB>>>((const float4*)emb, e0);

    // K2: histogram (4 edges per thread)
    hist_kernel<<<(NNZ_E / 4 + TPB - 1) / TPB, TPB>>>((const int4*)row);

    // K3: exclusive scan -> rowptr + cursors
    scan1_kernel<<<NBLK, SCAN_B>>>();
    scan2_kernel<<<1, 128>>>();
    scan3_kernel<<<NBLK, SCAN_B>>>();

    // K4: scatter to CSR
    scatter_kernel<<<(NNZ_E / 4 + TPB - 1) / TPB, TPB>>>(
        (const int4*)row, (const int4*)col, (const float4*)vals);

    // K5/K6: warp per row, fp16 gathers (sources selected device-side)
    const int WARPS_PER_BLOCK = TPB / 32;
    int spmm_blocks = (NROWS + WARPS_PER_BLOCK - 1) / WARPS_PER_BLOCK;

    // layer 1: e1 = A @ emb (gather g_embh), also g_e1h = fp16(e1)
    spmm_csr_kernel<0, true, false><<<spmm_blocks, TPB>>>(
        e1, nullptr, nullptr, nullptr);

    // layer 2: e2 = A @ e1 (gather g_e1h), fused summed = e0 + e1 + e2
    spmm_csr_kernel<1, false, true><<<spmm_blocks, TPB>>>(
        e2, (const float4*)e0, (const float4*)e1, summed);
}